// round 16
// baseline (speedup 1.0000x reference)
#include <cuda_runtime.h>
#include <cuda_bf16.h>
#include <math.h>

#define T_LEN 256
#define BATCH 64
#define INDIM 512
#define HDIM  1024
#define M_TOT (T_LEN * BATCH)   /* 16384 */
#define G4    (4 * HDIM)        /* 4096  */
#define NBLK_LSTM 128

/* packed-tile geometry: block = [32 k-pairs][stride] words (uint = bf16x2) */
#define BST 136                 /* GEMM A/B row stride (128 data + 8 pad) */
#define HST 72                  /* h-pack row stride (64 data + 8 pad)    */
#define HBLK_W (32 * HST)       /* 2304 words  = 9216 B  (64 k x 64 b)   */
#define HGRP_W (4 * HBLK_W)     /* 9216 words  = 36864 B (256 k)         */
#define HGRP_B (HGRP_W * 4)

/* ------------------------------------------------------------------ */
__device__ float    g_xproj [M_TOT * G4];
__device__ float    g_logits[M_TOT * INDIM];
__device__ __align__(256) unsigned g_hs_pk[T_LEN * 16 * HBLK_W];     /* h  bf16 packed */
__device__ __align__(256) unsigned g_apack[128 * 8 * 32 * BST];      /* inp  packed */
__device__ __align__(256) unsigned g_bx   [32 * 8 * 32 * BST];       /* Wxh  packed */
__device__ __align__(256) unsigned g_bo   [4 * 16 * 32 * BST];       /* Wout packed */
__device__ unsigned g_arr   [T_LEN][NBLK_LSTM];
__device__ unsigned g_epoch;
__device__ unsigned g_bar;

/* ------------------------------------------------------------------ */
__device__ __forceinline__ float sigmoidf_(float x) {
    return 1.0f / (1.0f + expf(-x));
}
__device__ __forceinline__ void mbar_init(unsigned mbar, unsigned cnt) {
    asm volatile("mbarrier.init.shared.b64 [%0], %1;" :: "r"(mbar), "r"(cnt) : "memory");
}
__device__ __forceinline__ void mbar_expect_tx(unsigned mbar, unsigned bytes) {
    asm volatile("mbarrier.arrive.expect_tx.shared.b64 _, [%0], %1;"
                 :: "r"(mbar), "r"(bytes) : "memory");
}
__device__ __forceinline__ void bulk_g2s(unsigned sdst, const void* gsrc,
                                         unsigned bytes, unsigned mbar) {
    asm volatile(
        "cp.async.bulk.shared::cluster.global.mbarrier::complete_tx::bytes "
        "[%0], [%1], %2, [%3];"
        :: "r"(sdst), "l"(gsrc), "r"(bytes), "r"(mbar) : "memory");
}
__device__ __forceinline__ void mbar_wait(unsigned mbar, unsigned parity) {
    asm volatile(
        "{\n\t.reg .pred P;\n\t"
        "WL_%=:\n\t"
        "mbarrier.try_wait.parity.acquire.cta.shared::cta.b64 P, [%0], %1, 0x989680;\n\t"
        "@P bra.uni WD_%=;\n\t"
        "bra.uni WL_%=;\n\t"
        "WD_%=:\n\t}"
        :: "r"(mbar), "r"(parity) : "memory");
}
/* bf16 mma m16n8k16 (fp32 accum) */
__device__ __forceinline__ void mma_bf16(float* c, const unsigned* a,
                                         const unsigned* b) {
    asm volatile(
        "mma.sync.aligned.m16n8k16.row.col.f32.bf16.bf16.f32 "
        "{%0,%1,%2,%3}, {%4,%5,%6,%7}, {%8,%9}, {%0,%1,%2,%3};"
        : "+f"(c[0]), "+f"(c[1]), "+f"(c[2]), "+f"(c[3])
        : "r"(a[0]), "r"(a[1]), "r"(a[2]), "r"(a[3]), "r"(b[0]), "r"(b[1]));
}

/* ------------------------------------------------------------------ */
/* pack fp32 [N][K] -> bf16 words [n>>7][kc][32 kp][136] + (n&127)    */
/* ------------------------------------------------------------------ */
__global__ __launch_bounds__(256)
void pack_bf16_kernel(const float* __restrict__ src, unsigned* __restrict__ dst,
                      int sh /*log2(K/2)*/, int kcCnt, int totalWords) {
    const int idx = blockIdx.x * 256 + threadIdx.x;
    if (idx >= totalWords) return;
    const int n  = idx >> sh;
    const int wp = idx & ((1 << sh) - 1);
    const int kc = wp >> 5, kp = wp & 31;
    const float2 v = *(const float2*)(src + ((size_t)n << (sh + 1)) + kc * 64 + kp * 2);
    __nv_bfloat162 b = __floats2bfloat162_rn(v.x, v.y);
    dst[(((size_t)(n >> 7) * kcCnt + kc) * 32 + kp) * BST + (n & 127)] =
        reinterpret_cast<unsigned&>(b);
}

/* ------------------------------------------------------------------ */
/* bf16 GEMM, bulk-staged packed tiles.                               */
/* C[m][n] = A[m][k]*B[n][k]^T + bias; MODE0: +img rows, C=g_xproj;   */
/* MODE1: A = packed h, C = g_logits.                                 */
/* ------------------------------------------------------------------ */
template <int KDIM, int NDIM, int MTILE, int AST, int MODE>
__global__ __launch_bounds__(256, 2)
void gemm_bf16(const float* __restrict__ bias,
               const float* __restrict__ img) {
    extern __shared__ __align__(16) unsigned sm[];
    constexpr int NS   = KDIM / 64;
    constexpr int AW   = 32 * AST;
    constexpr int BW   = 32 * BST;
    constexpr int BUFW = AW + BW;
    constexpr int MT   = MTILE / 32;
    constexpr int MH   = MTILE / 2;

    const unsigned* __restrict__ Apk = (MODE == 0) ? g_apack : g_hs_pk;
    const unsigned* __restrict__ Bpk = (MODE == 0) ? g_bx    : g_bo;
    float* __restrict__          Cp  = (MODE == 0) ? g_xproj : g_logits;

    const unsigned smb = (unsigned)__cvta_generic_to_shared(sm);
    const unsigned mb[2] = { smb + 2u * BUFW * 4u, smb + 2u * BUFW * 4u + 8u };

    const int tid = threadIdx.x, lane = tid & 31, warp = tid >> 5;
    const int wm = warp & 1, wn = warp >> 1;
    const int bm = blockIdx.y * MTILE, bn = blockIdx.x * 128;

    const unsigned* asrc = Apk + (size_t)blockIdx.y * NS * AW;
    const unsigned* bsrc = Bpk + (size_t)blockIdx.x * NS * BW;

    if (tid == 0) { mbar_init(mb[0], 1); mbar_init(mb[1], 1); }
    asm volatile("fence.proxy.async.shared::cta;" ::: "memory");
    __syncthreads();

    if (tid == 0) {
        mbar_expect_tx(mb[0], (AW + BW) * 4);
        bulk_g2s(smb,            asrc, AW * 4, mb[0]);
        bulk_g2s(smb + AW * 4u,  bsrc, BW * 4, mb[0]);
    }

    float acc[MT][4][4];
#pragma unroll
    for (int i = 0; i < MT; i++)
#pragma unroll
        for (int j = 0; j < 4; j++)
#pragma unroll
            for (int v = 0; v < 4; v++) acc[i][j][v] = 0.0f;

    int ph[2] = {0, 0};

    for (int s = 0; s < NS; s++) {
        const int buf = s & 1;
        mbar_wait(mb[buf], ph[buf]); ph[buf] ^= 1;
        __syncthreads();   /* everyone done with compute(s-1) -> buf^1 free */
        if (s + 1 < NS && tid == 0) {
            const int nb = buf ^ 1;
            mbar_expect_tx(mb[nb], (AW + BW) * 4);
            bulk_g2s(smb + (unsigned)nb * BUFW * 4u,
                     asrc + (size_t)(s + 1) * AW, AW * 4, mb[nb]);
            bulk_g2s(smb + (unsigned)nb * BUFW * 4u + AW * 4u,
                     bsrc + (size_t)(s + 1) * BW, BW * 4, mb[nb]);
        }
        const unsigned* As = sm + buf * BUFW;
        const unsigned* Bs = As + AW;
#pragma unroll
        for (int ks = 0; ks < 4; ks++) {
            const int kp = ks * 8 + (lane & 3);
            unsigned af[MT][4];
#pragma unroll
            for (int mt = 0; mt < MT; mt++) {
                const unsigned* a = As + kp * AST + wm * MH + mt * 16 + (lane >> 2);
                af[mt][0] = a[0];
                af[mt][1] = a[8];
                af[mt][2] = a[4 * AST];
                af[mt][3] = a[4 * AST + 8];
            }
#pragma unroll
            for (int nt = 0; nt < 4; nt++) {
                const unsigned* b = Bs + kp * BST + wn * 32 + nt * 8 + (lane >> 2);
                unsigned bf[2];
                bf[0] = b[0];
                bf[1] = b[4 * BST];
#pragma unroll
                for (int mt = 0; mt < MT; mt++)
                    mma_bf16(acc[mt][nt], af[mt], bf);
            }
        }
    }

    /* epilogue */
#pragma unroll
    for (int mt = 0; mt < MT; mt++) {
#pragma unroll
        for (int nt = 0; nt < 4; nt++) {
            const int m = bm + wm * MH + mt * 16 + (lane >> 2);
            const int n = bn + wn * 32 + nt * 8 + 2 * (lane & 3);
            const float2 bv = *(const float2*)&bias[n];
            float o0 = acc[mt][nt][0] + bv.x;
            float o1 = acc[mt][nt][1] + bv.y;
            float o2 = acc[mt][nt][2] + bv.x;
            float o3 = acc[mt][nt][3] + bv.y;
            if (MODE == 0) {
                if (m < BATCH) {
                    o0 += img[m * HDIM + (n & (HDIM - 1))];
                    o1 += img[m * HDIM + ((n + 1) & (HDIM - 1))];
                }
                if (m + 8 < BATCH) {
                    o2 += img[(m + 8) * HDIM + (n & (HDIM - 1))];
                    o3 += img[(m + 8) * HDIM + ((n + 1) & (HDIM - 1))];
                }
            }
            *(float2*)(Cp + (size_t)m * NDIM + n)       = make_float2(o0, o1);
            *(float2*)(Cp + (size_t)(m + 8) * NDIM + n) = make_float2(o2, o3);
        }
    }
}

/* ------------------------------------------------------------------ */
/* Persistent LSTM — bf16 mma, bulk staging from packed h layout.     */
/* h gmem: [t][kc 16][32 kp][72] words; LSTM stages 4 groups of 4     */
/* blocks; GEMM1 consumes the same layout directly (m-tile = 64 = t). */
/* smem (words): Ws[0,16512) | hs 2x9216 [16512,34944) |              */
/*               pre 2x2304 [34944,39552) | mbars [39552,39556)       */
/* ------------------------------------------------------------------ */
#define WSW 516
#define PST 36
#define W_WORDS    (32 * WSW)
#define HS_OFF_W   (W_WORDS)
#define PRE_OFF_W  (HS_OFF_W + 2 * HGRP_W)
#define PRE_SZ     (64 * PST)
#define MBAR_OFF_W (PRE_OFF_W + 2 * PRE_SZ)
#define LSTM_SMEM_W (MBAR_OFF_W + 8)

__global__ __launch_bounds__(256, 1)
void lstm_kernel(const float* __restrict__ Whh,
                 const float* __restrict__ bhh) {
    extern __shared__ __align__(16) unsigned smu[];
    unsigned* Ws  = smu;
    unsigned* hs0 = smu + HS_OFF_W;
    float*    pre = (float*)(smu + PRE_OFF_W);

    const unsigned smem_base = (unsigned)__cvta_generic_to_shared(smu);
    const unsigned mb[2] = { smem_base + MBAR_OFF_W * 4u,
                             smem_base + MBAR_OFF_W * 4u + 8u };
    const unsigned hs_sa  = smem_base + HS_OFF_W * 4u;

    const int tid  = threadIdx.x;
    const int lane = tid & 31;
    const int warp = tid >> 5;
    const int mg   = warp & 3;     /* 16-batch slice  */
    const int kg   = warp >> 2;    /* k half          */
    const int j0   = blockIdx.x * 8;
    const int bid  = blockIdx.x;

    const unsigned epoch = *(volatile unsigned*)&g_epoch;
    const unsigned tgt   = epoch + 1u;

    const int gb  = tid >> 2;
    const int gu0 = tid & 3;
    const int gu1 = gu0 + 4;

    /* stage Whh -> bf16 smem (once): Ws[r][k], r = u*4+g */
    for (int idx = tid; idx < 32 * 256; idx += 256) {
        const int r = idx & 31, k4 = idx >> 5;
        const int u = r >> 2, g = r & 3;
        float4 w = *(const float4*)&Whh[(size_t)(g * HDIM + j0 + u) * HDIM + k4 * 4];
        __nv_bfloat162 lo = __floats2bfloat162_rn(w.x, w.y);
        __nv_bfloat162 hi = __floats2bfloat162_rn(w.z, w.w);
        Ws[r * WSW + k4 * 2]     = reinterpret_cast<unsigned&>(lo);
        Ws[r * WSW + k4 * 2 + 1] = reinterpret_cast<unsigned&>(hi);
    }
    if (tid == 0) {
        mbar_init(mb[0], 1);
        mbar_init(mb[1], 1);
    }
    asm volatile("fence.proxy.async.shared::cta;" ::: "memory");

    float bh0[4], bh1[4];
#pragma unroll
    for (int g = 0; g < 4; g++) {
        bh0[g] = bhh[g * HDIM + j0 + gu0];
        bh1[g] = bhh[g * HDIM + j0 + gu1];
    }
    float c0 = 0.0f, c1 = 0.0f;
    int ph[2] = {0, 0};
    __syncthreads();

    for (int t = 0; t < T_LEN; t++) {
        /* xproj prefetch (overlaps the flag wait) */
        float xp0[4], xp1[4];
        {
            const float* xb = g_xproj + (size_t)t * BATCH * G4 + (size_t)gb * G4 + j0;
#pragma unroll
            for (int g = 0; g < 4; g++) {
                xp0[g] = __ldg(xb + g * HDIM + gu0);
                xp1[g] = __ldg(xb + g * HDIM + gu1);
            }
        }

        if (t > 0) {
            /* all-poll-all barrier: thread i<128 watches CTA i's flag */
            if (tid < NBLK_LSTM) {
                while (*(volatile unsigned*)&g_arr[t - 1][tid] < tgt) { }
            }
            __threadfence();
            __syncthreads();

            const char* __restrict__ hp =
                (const char*)g_hs_pk + (size_t)(t - 1) * 16 * HBLK_W * 4;

            if (tid == 0) {
                mbar_expect_tx(mb[0], HGRP_B);
                bulk_g2s(hs_sa, hp, HGRP_B, mb[0]);
            }

            float acc[4][4];
#pragma unroll
            for (int nt = 0; nt < 4; nt++)
#pragma unroll
                for (int v = 0; v < 4; v++) acc[nt][v] = 0.0f;

#pragma unroll 1
            for (int g = 0; g < 4; g++) {
                const int buf = g & 1;
                if (g < 3 && tid == 0) {
                    const int nb = (g + 1) & 1;
                    mbar_expect_tx(mb[nb], HGRP_B);
                    bulk_g2s(hs_sa + nb * HGRP_B,
                             hp + (size_t)(g + 1) * HGRP_B, HGRP_B, mb[nb]);
                }
                mbar_wait(mb[buf], ph[buf]);
                ph[buf] ^= 1;

                const unsigned* Agrp = hs0 + buf * HGRP_W;
#pragma unroll
                for (int blk2 = 0; blk2 < 2; blk2++) {
                    const unsigned* Ab = Agrp + (kg * 2 + blk2) * HBLK_W;
                    const int colbase = (g * 4 + kg * 2 + blk2) * 32;
#pragma unroll
                    for (int s = 0; s < 4; s++) {
                        const int cb = colbase + s * 8 + (lane & 3);
                        const unsigned* a = Ab + (s * 8 + (lane & 3)) * HST
                                            + mg * 16 + (lane >> 2);
                        unsigned af[4];
                        af[0] = a[0];
                        af[1] = a[8];
                        af[2] = a[4 * HST];
                        af[3] = a[4 * HST + 8];
#pragma unroll
                        for (int nt = 0; nt < 4; nt++) {
                            const unsigned* b = Ws + (nt * 8 + (lane >> 2)) * WSW + cb;
                            unsigned bf[2];
                            bf[0] = b[0];
                            bf[1] = b[4];
                            mma_bf16(acc[nt], af, bf);
                        }
                    }
                }
                __syncthreads();   /* buffer fully consumed before reuse */
            }

            {
                float* pg = pre + kg * PRE_SZ;
#pragma unroll
                for (int nt = 0; nt < 4; nt++) {
                    const int m = mg * 16 + (lane >> 2);
                    const int n = nt * 8 + 2 * (lane & 3);
                    *(float2*)&pg[m * PST + n]       = make_float2(acc[nt][0], acc[nt][1]);
                    *(float2*)&pg[(m + 8) * PST + n] = make_float2(acc[nt][2], acc[nt][3]);
                }
            }
        }
        __syncthreads();

        /* gate math: 2 cells per thread */
        {
            float s0[4], s1[4];
            if (t > 0) {
                float4 p00 = *(const float4*)&pre[gb * PST + gu0 * 4];
                float4 p01 = *(const float4*)&pre[PRE_SZ + gb * PST + gu0 * 4];
                float4 p10 = *(const float4*)&pre[gb * PST + gu1 * 4];
                float4 p11 = *(const float4*)&pre[PRE_SZ + gb * PST + gu1 * 4];
                s0[0] = p00.x + p01.x; s0[1] = p00.y + p01.y;
                s0[2] = p00.z + p01.z; s0[3] = p00.w + p01.w;
                s1[0] = p10.x + p11.x; s1[1] = p10.y + p11.y;
                s1[2] = p10.z + p11.z; s1[3] = p10.w + p11.w;
            } else {
#pragma unroll
                for (int g = 0; g < 4; g++) { s0[g] = 0.0f; s1[g] = 0.0f; }
            }
#pragma unroll
            for (int g = 0; g < 4; g++) {
                s0[g] += xp0[g] + bh0[g];
                s1[g] += xp1[g] + bh1[g];
            }
            unsigned short* hpk = (unsigned short*)g_hs_pk;
            {
                float ig = sigmoidf_(s0[0]), fg = sigmoidf_(s0[1]);
                float gg = tanhf(s0[2]),     og = sigmoidf_(s0[3]);
                c0 = fg * c0 + ig * gg;
                float hv = og * tanhf(c0);
                __nv_bfloat16 hb16 = __float2bfloat16(hv);
                const int u = j0 + gu0;
                const size_t w = (((size_t)t * 16 + (u >> 6)) * 32 +
                                  ((u & 63) >> 1)) * HST + gb;
                hpk[w * 2 + (u & 1)] = reinterpret_cast<unsigned short&>(hb16);
            }
            {
                float ig = sigmoidf_(s1[0]), fg = sigmoidf_(s1[1]);
                float gg = tanhf(s1[2]),     og = sigmoidf_(s1[3]);
                c1 = fg * c1 + ig * gg;
                float hv = og * tanhf(c1);
                __nv_bfloat16 hb16 = __float2bfloat16(hv);
                const int u = j0 + gu1;
                const size_t w = (((size_t)t * 16 + (u >> 6)) * 32 +
                                  ((u & 63) >> 1)) * HST + gb;
                hpk[w * 2 + (u & 1)] = reinterpret_cast<unsigned short&>(hb16);
            }
        }

        /* publish h(t): release fence then per-CTA flag */
        __threadfence();
        __syncthreads();
        if (tid == 0)
            *(volatile unsigned*)&g_arr[t][bid] = tgt;
    }

    /* final ticket barrier, then epoch++ (replay-safe) */
    if (tid == 0) {
        __threadfence();
        unsigned ticket = atomicAdd(&g_bar, 1u);
        unsigned target = (ticket / NBLK_LSTM + 1u) * NBLK_LSTM;
        while (*((volatile unsigned*)&g_bar) < target) { }
    }
    __syncthreads();
    if (bid == 0 && tid == 0) {
        __threadfence();
        *(volatile unsigned*)&g_epoch = epoch + 1u;
    }
}

/* ------------------------------------------------------------------ */
__global__ __launch_bounds__(256)
void logsoftmax_kernel(float* __restrict__ out) {
    __shared__ float red[8];
    const int row = blockIdx.x;
    const int tid = threadIdx.x;
    const float* x = g_logits + (size_t)row * INDIM;
    float v0 = x[tid];
    float v1 = x[tid + 256];

    float m = fmaxf(v0, v1);
#pragma unroll
    for (int o = 16; o; o >>= 1) m = fmaxf(m, __shfl_xor_sync(0xffffffffu, m, o));
    if ((tid & 31) == 0) red[tid >> 5] = m;
    __syncthreads();
    float M = fmaxf(fmaxf(fmaxf(red[0], red[1]), fmaxf(red[2], red[3])),
                    fmaxf(fmaxf(red[4], red[5]), fmaxf(red[6], red[7])));
    __syncthreads();

    float s = expf(v0 - M) + expf(v1 - M);
#pragma unroll
    for (int o = 16; o; o >>= 1) s += __shfl_xor_sync(0xffffffffu, s, o);
    if ((tid & 31) == 0) red[tid >> 5] = s;
    __syncthreads();
    float S = (red[0] + red[1]) + (red[2] + red[3]) +
              (red[4] + red[5]) + (red[6] + red[7]);
    float lse = M + logf(S);

    out[(size_t)row * INDIM + tid]       = v0 - lse;
    out[(size_t)row * INDIM + tid + 256] = v1 - lse;
}

/* ------------------------------------------------------------------ */
extern "C" void kernel_launch(void* const* d_in, const int* in_sizes, int n_in,
                              void* d_out, int out_size) {
    const float* inp  = (const float*)d_in[0];
    const float* img  = (const float*)d_in[1];
    const float* Wxh  = (const float*)d_in[2];
    const float* bxh  = (const float*)d_in[3];
    const float* Whh  = (const float*)d_in[4];
    const float* bhh  = (const float*)d_in[5];
    const float* Wout = (const float*)d_in[6];
    const float* bout = (const float*)d_in[7];
    float* out = (float*)d_out;

    unsigned *apack_p = nullptr, *bx_p = nullptr, *bo_p = nullptr;
    cudaGetSymbolAddress((void**)&apack_p, g_apack);
    cudaGetSymbolAddress((void**)&bx_p,    g_bx);
    cudaGetSymbolAddress((void**)&bo_p,    g_bo);

    const int g0_smem = (2 * (32 * BST + 32 * BST) + 8) * (int)sizeof(unsigned);
    const int g1_smem = (2 * (32 * HST + 32 * BST) + 8) * (int)sizeof(unsigned);
    const int lstm_smem = LSTM_SMEM_W * (int)sizeof(unsigned);      /* ~158 KB */

    cudaFuncSetAttribute(gemm_bf16<INDIM, G4, 128, BST, 0>,
                         cudaFuncAttributeMaxDynamicSharedMemorySize, g0_smem);
    cudaFuncSetAttribute(gemm_bf16<HDIM, INDIM, 64, HST, 1>,
                         cudaFuncAttributeMaxDynamicSharedMemorySize, g1_smem);
    cudaFuncSetAttribute(lstm_kernel,
                         cudaFuncAttributeMaxDynamicSharedMemorySize, lstm_smem);

    /* 0) pack inp / Wxh / Wout to bf16 tile blocks */
    pack_bf16_kernel<<<(M_TOT * 256 + 255) / 256, 256>>>(inp,  apack_p, 8, 8,  M_TOT * 256);
    pack_bf16_kernel<<<(G4    * 256 + 255) / 256, 256>>>(Wxh,  bx_p,    8, 8,  G4 * 256);
    pack_bf16_kernel<<<(INDIM * 512 + 255) / 256, 256>>>(Wout, bo_p,    9, 16, INDIM * 512);

    /* 1) xproj = inp @ Wxh^T + bxh (+ img4 on t=0 rows) */
    gemm_bf16<INDIM, G4, 128, BST, 0><<<dim3(G4 / 128, M_TOT / 128), 256, g0_smem>>>
        (bxh, img);

    /* 2) persistent LSTM recurrence -> g_hs_pk */
    lstm_kernel<<<NBLK_LSTM, 256, lstm_smem>>>(Whh, bhh);

    /* 3) logits = hs @ Wout^T + bout  (m-tile 64 = one timestep) */
    gemm_bf16<HDIM, INDIM, 64, HST, 1><<<dim3(INDIM / 128, T_LEN), 256, g1_smem>>>
        (bout, nullptr);

    /* 4) log_softmax -> d_out */
    logsoftmax_kernel<<<M_TOT, 256>>>(out);
}

// round 17
// speedup vs baseline: 1.2844x; 1.2844x over previous
#include <cuda_runtime.h>
#include <cuda_bf16.h>
#include <math.h>

#define T_LEN 256
#define BATCH 64
#define INDIM 512
#define HDIM  1024
#define M_TOT (T_LEN * BATCH)   /* 16384 */
#define G4    (4 * HDIM)        /* 4096  */
#define NBLK_LSTM 128

/* h chunk geometry (round-15 proven): 4 chunks of 256 k; rows 132 words */
#define HSW      132
#define HCHUNK_W (64 * HSW)                /* 8448 words = 33792 B */
#define HCHUNK_B (HCHUNK_W * 4)

/* packed GEMM0 tile geometry */
#define BST 136                 /* 128 data words + 8 pad */

/* ------------------------------------------------------------------ */
__device__ float    g_xproj [M_TOT * G4];
__device__ __align__(256) unsigned g_hs_bf[T_LEN * 4 * HCHUNK_W]; /* bf16 h chunks */
__device__ float    g_hs32  [M_TOT * HDIM];                       /* fp32 h (GEMM1) */
__device__ float    g_logits[M_TOT * INDIM];
__device__ __align__(256) unsigned g_apack[128 * 8 * 32 * BST];   /* inp packed */
__device__ __align__(256) unsigned g_bx   [32 * 8 * 32 * BST];    /* Wxh packed */
__device__ unsigned g_arr   [T_LEN][NBLK_LSTM];
__device__ unsigned g_epoch;
__device__ unsigned g_bar;

/* ------------------------------------------------------------------ */
__device__ __forceinline__ float sigmoidf_(float x) {
    return 1.0f / (1.0f + expf(-x));
}
__device__ __forceinline__ void cp_async16(float* smem_dst, const float* gsrc) {
    unsigned sa = (unsigned)__cvta_generic_to_shared(smem_dst);
    asm volatile("cp.async.cg.shared.global [%0], [%1], 16;\n" :: "r"(sa), "l"(gsrc));
}
__device__ __forceinline__ void cp_commit() {
    asm volatile("cp.async.commit_group;\n" ::: "memory");
}
__device__ __forceinline__ void cp_wait0() {
    asm volatile("cp.async.wait_group 0;\n" ::: "memory");
}
__device__ __forceinline__ void cp_wait1() {
    asm volatile("cp.async.wait_group 1;\n" ::: "memory");
}
__device__ __forceinline__ void mbar_init(unsigned mbar, unsigned cnt) {
    asm volatile("mbarrier.init.shared.b64 [%0], %1;" :: "r"(mbar), "r"(cnt) : "memory");
}
__device__ __forceinline__ void mbar_expect_tx(unsigned mbar, unsigned bytes) {
    asm volatile("mbarrier.arrive.expect_tx.shared.b64 _, [%0], %1;"
                 :: "r"(mbar), "r"(bytes) : "memory");
}
__device__ __forceinline__ void bulk_g2s(unsigned sdst, const void* gsrc,
                                         unsigned bytes, unsigned mbar) {
    asm volatile(
        "cp.async.bulk.shared::cluster.global.mbarrier::complete_tx::bytes "
        "[%0], [%1], %2, [%3];"
        :: "r"(sdst), "l"(gsrc), "r"(bytes), "r"(mbar) : "memory");
}
__device__ __forceinline__ void mbar_wait(unsigned mbar, unsigned parity) {
    asm volatile(
        "{\n\t.reg .pred P;\n\t"
        "WL_%=:\n\t"
        "mbarrier.try_wait.parity.acquire.cta.shared::cta.b64 P, [%0], %1, 0x989680;\n\t"
        "@P bra.uni WD_%=;\n\t"
        "bra.uni WL_%=;\n\t"
        "WD_%=:\n\t}"
        :: "r"(mbar), "r"(parity) : "memory");
}
/* tf32 mma m16n8k8 (fp32 accum) */
__device__ __forceinline__ void mma_tf32(float* c, const unsigned* a,
                                         const unsigned* b) {
    asm volatile(
        "mma.sync.aligned.m16n8k8.row.col.f32.tf32.tf32.f32 "
        "{%0,%1,%2,%3}, {%4,%5,%6,%7}, {%8,%9}, {%0,%1,%2,%3};"
        : "+f"(c[0]), "+f"(c[1]), "+f"(c[2]), "+f"(c[3])
        : "r"(a[0]), "r"(a[1]), "r"(a[2]), "r"(a[3]), "r"(b[0]), "r"(b[1]));
}
/* bf16 mma m16n8k16 (fp32 accum) */
__device__ __forceinline__ void mma_bf16(float* c, const unsigned* a,
                                         const unsigned* b) {
    asm volatile(
        "mma.sync.aligned.m16n8k16.row.col.f32.bf16.bf16.f32 "
        "{%0,%1,%2,%3}, {%4,%5,%6,%7}, {%8,%9}, {%0,%1,%2,%3};"
        : "+f"(c[0]), "+f"(c[1]), "+f"(c[2]), "+f"(c[3])
        : "r"(a[0]), "r"(a[1]), "r"(a[2]), "r"(a[3]), "r"(b[0]), "r"(b[1]));
}
__device__ __forceinline__ unsigned fbits(float x) { return __float_as_uint(x); }

/* ------------------------------------------------------------------ */
/* pack fp32 [N][512] -> bf16 words [n>>7][kc 8][32 kp][136] + (n&127)*/
/* ------------------------------------------------------------------ */
__global__ __launch_bounds__(256)
void pack_bf16_kernel(const float* __restrict__ src, unsigned* __restrict__ dst,
                      int totalWords) {
    const int idx = blockIdx.x * 256 + threadIdx.x;
    if (idx >= totalWords) return;
    const int n  = idx >> 8;
    const int wp = idx & 255;
    const int kc = wp >> 5, kp = wp & 31;
    const float2 v = *(const float2*)(src + ((size_t)n << 9) + kc * 64 + kp * 2);
    __nv_bfloat162 b = __floats2bfloat162_rn(v.x, v.y);
    dst[(((size_t)(n >> 7) * 8 + kc) * 32 + kp) * BST + (n & 127)] =
        reinterpret_cast<unsigned&>(b);
}

/* ------------------------------------------------------------------ */
/* GEMM0: bf16, bulk-staged packed tiles (round-16 proven: 192 us).   */
/* xproj[m][n] = inp[m][k]*Wxh[n][k]^T + bxh (+ img4 rows m<64)       */
/* ------------------------------------------------------------------ */
__global__ __launch_bounds__(256, 2)
void gemm_bf16_g0(const float* __restrict__ bias,
                  const float* __restrict__ img) {
    extern __shared__ __align__(16) unsigned sm[];
    constexpr int NS   = 8;             /* 512 k / 64 */
    constexpr int AW   = 32 * BST;
    constexpr int BW   = 32 * BST;
    constexpr int BUFW = AW + BW;

    const unsigned smb = (unsigned)__cvta_generic_to_shared(sm);
    const unsigned mb[2] = { smb + 2u * BUFW * 4u, smb + 2u * BUFW * 4u + 8u };

    const int tid = threadIdx.x, lane = tid & 31, warp = tid >> 5;
    const int wm = warp & 1, wn = warp >> 1;
    const int bm = blockIdx.y * 128, bn = blockIdx.x * 128;

    const unsigned* asrc = g_apack + (size_t)blockIdx.y * NS * AW;
    const unsigned* bsrc = g_bx    + (size_t)blockIdx.x * NS * BW;

    if (tid == 0) { mbar_init(mb[0], 1); mbar_init(mb[1], 1); }
    asm volatile("fence.proxy.async.shared::cta;" ::: "memory");
    __syncthreads();

    if (tid == 0) {
        mbar_expect_tx(mb[0], (AW + BW) * 4);
        bulk_g2s(smb,           asrc, AW * 4, mb[0]);
        bulk_g2s(smb + AW * 4u, bsrc, BW * 4, mb[0]);
    }

    float acc[4][4][4];
#pragma unroll
    for (int i = 0; i < 4; i++)
#pragma unroll
        for (int j = 0; j < 4; j++)
#pragma unroll
            for (int v = 0; v < 4; v++) acc[i][j][v] = 0.0f;

    int ph[2] = {0, 0};

    for (int s = 0; s < NS; s++) {
        const int buf = s & 1;
        mbar_wait(mb[buf], ph[buf]); ph[buf] ^= 1;
        __syncthreads();
        if (s + 1 < NS && tid == 0) {
            const int nb = buf ^ 1;
            mbar_expect_tx(mb[nb], (AW + BW) * 4);
            bulk_g2s(smb + (unsigned)nb * BUFW * 4u,
                     asrc + (size_t)(s + 1) * AW, AW * 4, mb[nb]);
            bulk_g2s(smb + (unsigned)nb * BUFW * 4u + AW * 4u,
                     bsrc + (size_t)(s + 1) * BW, BW * 4, mb[nb]);
        }
        const unsigned* As = sm + buf * BUFW;
        const unsigned* Bs = As + AW;
#pragma unroll
        for (int ks = 0; ks < 4; ks++) {
            const int kp = ks * 8 + (lane & 3);
            unsigned af[4][4];
#pragma unroll
            for (int mt = 0; mt < 4; mt++) {
                const unsigned* a = As + kp * BST + wm * 64 + mt * 16 + (lane >> 2);
                af[mt][0] = a[0];
                af[mt][1] = a[8];
                af[mt][2] = a[4 * BST];
                af[mt][3] = a[4 * BST + 8];
            }
#pragma unroll
            for (int nt = 0; nt < 4; nt++) {
                const unsigned* b = Bs + kp * BST + wn * 32 + nt * 8 + (lane >> 2);
                unsigned bf[2];
                bf[0] = b[0];
                bf[1] = b[4 * BST];
#pragma unroll
                for (int mt = 0; mt < 4; mt++)
                    mma_bf16(acc[mt][nt], af[mt], bf);
            }
        }
    }

#pragma unroll
    for (int mt = 0; mt < 4; mt++) {
#pragma unroll
        for (int nt = 0; nt < 4; nt++) {
            const int m = bm + wm * 64 + mt * 16 + (lane >> 2);
            const int n = bn + wn * 32 + nt * 8 + 2 * (lane & 3);
            const float2 bv = *(const float2*)&bias[n];
            float o0 = acc[mt][nt][0] + bv.x;
            float o1 = acc[mt][nt][1] + bv.y;
            float o2 = acc[mt][nt][2] + bv.x;
            float o3 = acc[mt][nt][3] + bv.y;
            if (m < BATCH) {
                o0 += img[m * HDIM + (n & (HDIM - 1))];
                o1 += img[m * HDIM + ((n + 1) & (HDIM - 1))];
            }
            if (m + 8 < BATCH) {
                o2 += img[(m + 8) * HDIM + (n & (HDIM - 1))];
                o3 += img[(m + 8) * HDIM + ((n + 1) & (HDIM - 1))];
            }
            *(float2*)(g_xproj + (size_t)m * G4 + n)       = make_float2(o0, o1);
            *(float2*)(g_xproj + (size_t)(m + 8) * G4 + n) = make_float2(o2, o3);
        }
    }
}

/* ------------------------------------------------------------------ */
/* GEMM1: tf32, cp.async (round-15 proven). logits = hs32 @ Wout^T.   */
/* ------------------------------------------------------------------ */
#define GST 36

__global__ __launch_bounds__(256, 2)
void gemm_tf32_g1(const float* __restrict__ B,
                  const float* __restrict__ bias) {
    extern __shared__ __align__(16) float smf[];
    const float* __restrict__ Ap = g_hs32;
    float* __restrict__       Cp = g_logits;
    constexpr int KDIM = HDIM, NDIM = INDIM;

    const int bm   = blockIdx.y * 128;
    const int bn   = blockIdx.x * 128;
    const int tid  = threadIdx.x;
    const int lane = tid & 31;
    const int warp = tid >> 5;
    const int wm   = warp & 1;
    const int wn   = warp >> 1;

    float acc[4][4][4];
#pragma unroll
    for (int i = 0; i < 4; i++)
#pragma unroll
        for (int j = 0; j < 4; j++)
#pragma unroll
            for (int v = 0; v < 4; v++) acc[i][j][v] = 0.0f;

    const int NCH = KDIM / 32;

    {
        float* As = smf;
        float* Bs = smf + 128 * GST;
#pragma unroll
        for (int i = 0; i < 4; i++) {
            const int idx = tid + i * 256;
            const int row = idx >> 3, q = idx & 7;
            cp_async16(&As[row * GST + q * 4], Ap + (size_t)(bm + row) * KDIM + q * 4);
            cp_async16(&Bs[row * GST + q * 4], B  + (size_t)(bn + row) * KDIM + q * 4);
        }
        cp_commit();
    }

    for (int ck = 0; ck < NCH; ck++) {
        const int buf = ck & 1;
        if (ck + 1 < NCH) {
            float* As = smf + ((ck + 1) & 1) * (256 * GST);
            float* Bs = As + 128 * GST;
            const int kt = (ck + 1) * 32;
#pragma unroll
            for (int i = 0; i < 4; i++) {
                const int idx = tid + i * 256;
                const int row = idx >> 3, q = idx & 7;
                cp_async16(&As[row * GST + q * 4],
                           Ap + (size_t)(bm + row) * KDIM + kt + q * 4);
                cp_async16(&Bs[row * GST + q * 4],
                           B + (size_t)(bn + row) * KDIM + kt + q * 4);
            }
            cp_commit();
            cp_wait1();
        } else {
            cp_wait0();
        }
        __syncthreads();

        const float* As = smf + buf * (256 * GST) + (wm * 64) * GST;
        const float* Bs = smf + buf * (256 * GST) + 128 * GST + (wn * 32) * GST;
#pragma unroll
        for (int ks = 0; ks < 4; ks++) {
            const int col = ks * 8 + (lane & 3);
            unsigned af[4][4];
#pragma unroll
            for (int mt = 0; mt < 4; mt++) {
                const int row = mt * 16 + (lane >> 2);
                af[mt][0] = fbits(As[row * GST + col]);
                af[mt][1] = fbits(As[(row + 8) * GST + col]);
                af[mt][2] = fbits(As[row * GST + col + 4]);
                af[mt][3] = fbits(As[(row + 8) * GST + col + 4]);
            }
#pragma unroll
            for (int nt = 0; nt < 4; nt++) {
                const int nr = nt * 8 + (lane >> 2);
                unsigned bf[2];
                bf[0] = fbits(Bs[nr * GST + col]);
                bf[1] = fbits(Bs[nr * GST + col + 4]);
#pragma unroll
                for (int mt = 0; mt < 4; mt++)
                    mma_tf32(acc[mt][nt], af[mt], bf);
            }
        }
        __syncthreads();
    }

#pragma unroll
    for (int mt = 0; mt < 4; mt++) {
#pragma unroll
        for (int nt = 0; nt < 4; nt++) {
            const int m = bm + wm * 64 + mt * 16 + (lane >> 2);
            const int n = bn + wn * 32 + nt * 8 + 2 * (lane & 3);
            const float2 bv = *(const float2*)&bias[n];
            *(float2*)(Cp + (size_t)m * NDIM + n) =
                make_float2(acc[mt][nt][0] + bv.x, acc[mt][nt][1] + bv.y);
            *(float2*)(Cp + (size_t)(m + 8) * NDIM + n) =
                make_float2(acc[mt][nt][2] + bv.x, acc[mt][nt][3] + bv.y);
        }
    }
}

/* ------------------------------------------------------------------ */
/* Persistent LSTM — round-15 verbatim (proven fastest).              */
/* ------------------------------------------------------------------ */
#define WSW 516
#define PST 36
#define W_WORDS   (32 * WSW)
#define HS_OFF_W  (W_WORDS)
#define PRE_OFF_W (HS_OFF_W + 2 * HCHUNK_W)
#define PRE_SZ    (64 * PST)
#define MBAR_OFF_W (PRE_OFF_W + 2 * PRE_SZ)
#define LSTM_SMEM_W (MBAR_OFF_W + 8)

__global__ __launch_bounds__(256, 1)
void lstm_kernel(const float* __restrict__ Whh,
                 const float* __restrict__ bhh) {
    extern __shared__ __align__(16) unsigned smu[];
    unsigned* Ws  = smu;
    unsigned* hs0 = smu + HS_OFF_W;
    float*    pre = (float*)(smu + PRE_OFF_W);

    const unsigned smem_base = (unsigned)__cvta_generic_to_shared(smu);
    const unsigned mb[2] = { smem_base + MBAR_OFF_W * 4u,
                             smem_base + MBAR_OFF_W * 4u + 8u };
    const unsigned hs_sa  = smem_base + HS_OFF_W * 4u;

    const int tid  = threadIdx.x;
    const int lane = tid & 31;
    const int warp = tid >> 5;
    const int mg   = warp & 3;
    const int kg   = warp >> 2;
    const int j0   = blockIdx.x * 8;
    const int bid  = blockIdx.x;
    const int chown = bid >> 5;

    const unsigned epoch = *(volatile unsigned*)&g_epoch;
    const unsigned tgt   = epoch + 1u;

    const int gb  = tid >> 2;
    const int gu0 = tid & 3;
    const int gu1 = gu0 + 4;

    for (int idx = tid; idx < 32 * 256; idx += 256) {
        const int r = idx & 31, k4 = idx >> 5;
        const int u = r >> 2, g = r & 3;
        float4 w = *(const float4*)&Whh[(size_t)(g * HDIM + j0 + u) * HDIM + k4 * 4];
        __nv_bfloat162 lo = __floats2bfloat162_rn(w.x, w.y);
        __nv_bfloat162 hi = __floats2bfloat162_rn(w.z, w.w);
        Ws[r * WSW + k4 * 2]     = reinterpret_cast<unsigned&>(lo);
        Ws[r * WSW + k4 * 2 + 1] = reinterpret_cast<unsigned&>(hi);
    }
    if (tid == 0) {
        mbar_init(mb[0], 1);
        mbar_init(mb[1], 1);
    }
    asm volatile("fence.proxy.async.shared::cta;" ::: "memory");

    float bh0[4], bh1[4];
#pragma unroll
    for (int g = 0; g < 4; g++) {
        bh0[g] = bhh[g * HDIM + j0 + gu0];
        bh1[g] = bhh[g * HDIM + j0 + gu1];
    }
    float c0 = 0.0f, c1 = 0.0f;
    int ph[2] = {0, 0};
    __syncthreads();

    for (int t = 0; t < T_LEN; t++) {
        float xp0[4], xp1[4];
        {
            const float* xb = g_xproj + (size_t)t * BATCH * G4 + (size_t)gb * G4 + j0;
#pragma unroll
            for (int g = 0; g < 4; g++) {
                xp0[g] = __ldg(xb + g * HDIM + gu0);
                xp1[g] = __ldg(xb + g * HDIM + gu1);
            }
        }

        if (t > 0) {
            if (tid < NBLK_LSTM) {
                while (*(volatile unsigned*)&g_arr[t - 1][tid] < tgt) { }
            }
            __threadfence();
            __syncthreads();

            const char* __restrict__ hp =
                (const char*)g_hs_bf + (size_t)(t - 1) * 4 * HCHUNK_B;

            if (tid == 0) {
                mbar_expect_tx(mb[0], HCHUNK_B);
                bulk_g2s(hs_sa, hp, HCHUNK_B, mb[0]);
            }

            float acc[4][4];
#pragma unroll
            for (int nt = 0; nt < 4; nt++)
#pragma unroll
                for (int v = 0; v < 4; v++) acc[nt][v] = 0.0f;

#pragma unroll 1
            for (int ch = 0; ch < 4; ch++) {
                const int buf = ch & 1;
                if (ch < 3 && tid == 0) {
                    const int nb = (ch + 1) & 1;
                    mbar_expect_tx(mb[nb], HCHUNK_B);
                    bulk_g2s(hs_sa + nb * HCHUNK_B,
                             hp + (size_t)(ch + 1) * HCHUNK_B, HCHUNK_B, mb[nb]);
                }
                mbar_wait(mb[buf], ph[buf]);
                ph[buf] ^= 1;

                const unsigned* Ab = hs0 + buf * HCHUNK_W
                                     + (mg * 16) * HSW + kg * 64;
                const unsigned* Wb = Ws + ch * 128 + kg * 64;
#pragma unroll
                for (int ks = 0; ks < 8; ks++) {
                    const int colw = ks * 8 + (lane & 3);
                    unsigned af[4];
                    {
                        const unsigned* a = Ab + (lane >> 2) * HSW + colw;
                        af[0] = a[0];
                        af[1] = a[8 * HSW];
                        af[2] = a[4];
                        af[3] = a[8 * HSW + 4];
                    }
#pragma unroll
                    for (int nt = 0; nt < 4; nt++) {
                        const unsigned* b = Wb + (nt * 8 + (lane >> 2)) * WSW + colw;
                        unsigned bf[2];
                        bf[0] = b[0];
                        bf[1] = b[4];
                        mma_bf16(acc[nt], af, bf);
                    }
                }
                __syncthreads();
            }

            {
                float* pg = pre + kg * PRE_SZ;
#pragma unroll
                for (int nt = 0; nt < 4; nt++) {
                    const int m = mg * 16 + (lane >> 2);
                    const int n = nt * 8 + 2 * (lane & 3);
                    *(float2*)&pg[m * PST + n]       = make_float2(acc[nt][0], acc[nt][1]);
                    *(float2*)&pg[(m + 8) * PST + n] = make_float2(acc[nt][2], acc[nt][3]);
                }
            }
        }
        __syncthreads();

        {
            float s0[4], s1[4];
            if (t > 0) {
                float4 p00 = *(const float4*)&pre[gb * PST + gu0 * 4];
                float4 p01 = *(const float4*)&pre[PRE_SZ + gb * PST + gu0 * 4];
                float4 p10 = *(const float4*)&pre[gb * PST + gu1 * 4];
                float4 p11 = *(const float4*)&pre[PRE_SZ + gb * PST + gu1 * 4];
                s0[0] = p00.x + p01.x; s0[1] = p00.y + p01.y;
                s0[2] = p00.z + p01.z; s0[3] = p00.w + p01.w;
                s1[0] = p10.x + p11.x; s1[1] = p10.y + p11.y;
                s1[2] = p10.z + p11.z; s1[3] = p10.w + p11.w;
            } else {
#pragma unroll
                for (int g = 0; g < 4; g++) { s0[g] = 0.0f; s1[g] = 0.0f; }
            }
#pragma unroll
            for (int g = 0; g < 4; g++) {
                s0[g] += xp0[g] + bh0[g];
                s1[g] += xp1[g] + bh1[g];
            }
            unsigned short* hb =
                (unsigned short*)g_hs_bf +
                ((size_t)(t * 4 + chown) * 64 + gb) * (HSW * 2) + (j0 & 255);
            float* h32 = g_hs32 + (size_t)t * BATCH * HDIM + (size_t)gb * HDIM + j0;
            {
                float ig = sigmoidf_(s0[0]), fg = sigmoidf_(s0[1]);
                float gg = tanhf(s0[2]),     og = sigmoidf_(s0[3]);
                c0 = fg * c0 + ig * gg;
                float hv = og * tanhf(c0);
                __nv_bfloat16 hb16 = __float2bfloat16(hv);
                hb[gu0]  = reinterpret_cast<unsigned short&>(hb16);
                h32[gu0] = hv;
            }
            {
                float ig = sigmoidf_(s1[0]), fg = sigmoidf_(s1[1]);
                float gg = tanhf(s1[2]),     og = sigmoidf_(s1[3]);
                c1 = fg * c1 + ig * gg;
                float hv = og * tanhf(c1);
                __nv_bfloat16 hb16 = __float2bfloat16(hv);
                hb[gu1]  = reinterpret_cast<unsigned short&>(hb16);
                h32[gu1] = hv;
            }
        }

        __threadfence();
        __syncthreads();
        if (tid == 0)
            *(volatile unsigned*)&g_arr[t][bid] = tgt;
    }

    if (tid == 0) {
        __threadfence();
        unsigned ticket = atomicAdd(&g_bar, 1u);
        unsigned target = (ticket / NBLK_LSTM + 1u) * NBLK_LSTM;
        while (*((volatile unsigned*)&g_bar) < target) { }
    }
    __syncthreads();
    if (bid == 0 && tid == 0) {
        __threadfence();
        *(volatile unsigned*)&g_epoch = epoch + 1u;
    }
}

/* ------------------------------------------------------------------ */
__global__ __launch_bounds__(256)
void logsoftmax_kernel(float* __restrict__ out) {
    __shared__ float red[8];
    const int row = blockIdx.x;
    const int tid = threadIdx.x;
    const float* x = g_logits + (size_t)row * INDIM;
    float v0 = x[tid];
    float v1 = x[tid + 256];

    float m = fmaxf(v0, v1);
#pragma unroll
    for (int o = 16; o; o >>= 1) m = fmaxf(m, __shfl_xor_sync(0xffffffffu, m, o));
    if ((tid & 31) == 0) red[tid >> 5] = m;
    __syncthreads();
    float M = fmaxf(fmaxf(fmaxf(red[0], red[1]), fmaxf(red[2], red[3])),
                    fmaxf(fmaxf(red[4], red[5]), fmaxf(red[6], red[7])));
    __syncthreads();

    float s = expf(v0 - M) + expf(v1 - M);
#pragma unroll
    for (int o = 16; o; o >>= 1) s += __shfl_xor_sync(0xffffffffu, s, o);
    if ((tid & 31) == 0) red[tid >> 5] = s;
    __syncthreads();
    float S = (red[0] + red[1]) + (red[2] + red[3]) +
              (red[4] + red[5]) + (red[6] + red[7]);
    float lse = M + logf(S);

    out[(size_t)row * INDIM + tid]       = v0 - lse;
    out[(size_t)row * INDIM + tid + 256] = v1 - lse;
}

/* ------------------------------------------------------------------ */
extern "C" void kernel_launch(void* const* d_in, const int* in_sizes, int n_in,
                              void* d_out, int out_size) {
    const float* inp  = (const float*)d_in[0];
    const float* img  = (const float*)d_in[1];
    const float* Wxh  = (const float*)d_in[2];
    const float* bxh  = (const float*)d_in[3];
    const float* Whh  = (const float*)d_in[4];
    const float* bhh  = (const float*)d_in[5];
    const float* Wout = (const float*)d_in[6];
    const float* bout = (const float*)d_in[7];
    float* out = (float*)d_out;

    unsigned *apack_p = nullptr, *bx_p = nullptr;
    cudaGetSymbolAddress((void**)&apack_p, g_apack);
    cudaGetSymbolAddress((void**)&bx_p,    g_bx);

    const int g0_smem = (2 * 2 * 32 * BST + 8) * (int)sizeof(unsigned);   /* 69.7 KB  */
    const int g1_smem = 2 * 2 * 128 * GST * (int)sizeof(float);           /* 73.7 KB  */
    const int lstm_smem = LSTM_SMEM_W * (int)sizeof(unsigned);            /* ~152 KB  */

    cudaFuncSetAttribute(gemm_bf16_g0,
                         cudaFuncAttributeMaxDynamicSharedMemorySize, g0_smem);
    cudaFuncSetAttribute(gemm_tf32_g1,
                         cudaFuncAttributeMaxDynamicSharedMemorySize, g1_smem);
    cudaFuncSetAttribute(lstm_kernel,
                         cudaFuncAttributeMaxDynamicSharedMemorySize, lstm_smem);

    /* 0) pack inp / Wxh to bf16 tile blocks */
    pack_bf16_kernel<<<(M_TOT * 256 + 255) / 256, 256>>>(inp, apack_p, M_TOT * 256);
    pack_bf16_kernel<<<(G4    * 256 + 255) / 256, 256>>>(Wxh, bx_p,    G4 * 256);

    /* 1) xproj = inp @ Wxh^T + bxh (+ img4 on t=0 rows) — packed bulk bf16 */
    gemm_bf16_g0<<<dim3(G4 / 128, M_TOT / 128), 256, g0_smem>>>(bxh, img);

    /* 2) persistent LSTM recurrence (round-15) */
    lstm_kernel<<<NBLK_LSTM, 256, lstm_smem>>>(Whh, bhh);

    /* 3) logits = hs32 @ Wout^T + bout — tf32 */
    gemm_tf32_g1<<<dim3(INDIM / 128, M_TOT / 128), 256, g1_smem>>>(Wout, bout);

    /* 4) log_softmax -> d_out */
    logsoftmax_kernel<<<M_TOT, 256>>>(out);
}